// round 8
// baseline (speedup 1.0000x reference)
#include <cuda_runtime.h>
#include <cuda_fp16.h>
#include <math.h>
#include <stdint.h>

// ---------------------------------------------------------------------------
// Problem constants
// ---------------------------------------------------------------------------
#define NB    128
#define LSEQ  128
#define DIM   768
#define NF    1024
#define LOUT  126
#define NROWS (NB * LSEQ)

#define K2    1536
#define K3    2304
#define K4    3072
#define KTOT  3072
#define KC    64             // K per chunk (fp16 elems) -> 128B row
#define NCHUNK (KTOT / KC)   // 48
#define PH1   (K2 / KC)      // 24: chunks with 3 active branches
#define PH2   (K3 / KC)      // 36: chunks with 2 active branches

#define NTHR  512            // 16 warps: 4 m-groups x 4 n-groups

// smem layout (bytes)
#define A_STRIDE  144                      // 64 fp16 (128B) + 16B pad
#define STAGE_A   (128 * A_STRIDE)         // 18432
#define STAGE_B1  (64 * A_STRIDE)          // 9216
#define STAGE_SZ  (STAGE_A + 3 * STAGE_B1) // 46080
#define NSTAGE    4
#define SMEM_DYN  (NSTAGE * STAGE_SZ)      // 184320

// ---------------------------------------------------------------------------
// Scratch (device globals; no allocations allowed)
// ---------------------------------------------------------------------------
__device__ __half g_X[(NROWS + 8) * DIM];
#define WTOT (NF * (K2 + K3 + K4))
__device__ __half g_W[WTOT];
__device__ float g_part[NB * 8 * 128];
__device__ float g_rn[NB * 128];

// ---------------------------------------------------------------------------
// Baseline-PTX helpers (sm_80-class; compile under compute_103)
// ---------------------------------------------------------------------------
static __device__ __forceinline__ uint32_t smem_u32(const void* p) {
    uint32_t a;
    asm("{ .reg .u64 t; cvta.to.shared.u64 t, %1; cvt.u32.u64 %0, t; }"
        : "=r"(a) : "l"(p));
    return a;
}

#define CP_ASYNC16(dst, src) \
    asm volatile("cp.async.cg.shared.global [%0], [%1], 16;" \
                 :: "r"(dst), "l"(src) : "memory")
#define CP_COMMIT() asm volatile("cp.async.commit_group;" ::: "memory")
#define CP_WAIT(n)  asm volatile("cp.async.wait_group %0;" :: "n"(n) : "memory")

#define LDMX4(r, addr) \
    asm volatile("ldmatrix.sync.aligned.m8n8.x4.shared.b16 {%0,%1,%2,%3}, [%4];" \
                 : "=r"((r)[0]), "=r"((r)[1]), "=r"((r)[2]), "=r"((r)[3]) \
                 : "r"(addr))

#define MMA16816(d, a, b0v, b1v) \
    asm volatile("mma.sync.aligned.m16n8k16.row.col.f32.f16.f16.f32 " \
                 "{%0,%1,%2,%3},{%4,%5,%6,%7},{%8,%9},{%0,%1,%2,%3};" \
                 : "+f"((d)[0]), "+f"((d)[1]), "+f"((d)[2]), "+f"((d)[3]) \
                 : "r"((a)[0]), "r"((a)[1]), "r"((a)[2]), "r"((a)[3]), \
                   "r"(b0v), "r"(b1v))

// ---------------------------------------------------------------------------
// Prep: fp32 -> fp16
// ---------------------------------------------------------------------------
__global__ void cvt_x_kernel(const float* __restrict__ X) {
    const int n2 = (NROWS + 8) * DIM / 2;
    const int lim2 = NROWS * DIM / 2;
    __half2* dst = (__half2*)g_X;
    for (int i = blockIdx.x * blockDim.x + threadIdx.x; i < n2; i += gridDim.x * blockDim.x) {
        float2 v = (i < lim2) ? *(const float2*)(X + 2 * i) : make_float2(0.f, 0.f);
        dst[i] = __floats2half2_rn(v.x, v.y);
    }
}

__global__ void cvt_w_kernel(const float* __restrict__ W2, const float* __restrict__ W3,
                             const float* __restrict__ W4) {
    const int n2 = WTOT / 2;
    __half2* dst = (__half2*)g_W;
    for (int i = blockIdx.x * blockDim.x + threadIdx.x; i < n2; i += gridDim.x * blockDim.x) {
        int j = 2 * i;
        const float* src;
        if (j < NF * K2)             src = W2 + j;
        else if (j < NF * (K2 + K3)) src = W3 + (j - NF * K2);
        else                         src = W4 + (j - NF * (K2 + K3));
        float2 v = *(const float2*)src;
        dst[i] = __floats2half2_rn(v.x, v.y);
    }
}

// ---------------------------------------------------------------------------
// Per-chunk compute body. NBR = number of active branches (the LAST NBR of
// {K2,K3,K4}); fully compile-time. Warp tile 32 pos x 16 feat.
// ---------------------------------------------------------------------------
template<int NBR>
static __device__ __forceinline__ void do_chunk(
    uint32_t sA, int lane, int wm, int wn, float (&acc)[3][2][2][4])
{
    // A fragments [mt][ks][4]: 16x16 tiles
    uint32_t afr[2][4][4];
    #pragma unroll
    for (int mt = 0; mt < 2; ++mt)
        #pragma unroll
        for (int ks = 0; ks < 4; ++ks) {
            int m = wm * 32 + mt * 16 + (lane & 7) + ((lane >> 3) & 1) * 8;
            int k = ks * 16 + (lane >> 4) * 8;
            LDMX4(afr[mt][ks], sA + m * A_STRIDE + k * 2);
        }

    #pragma unroll
    for (int biR = 0; biR < NBR; ++biR) {
        const int bi = 3 - NBR + biR;
        const uint32_t sB = sA + STAGE_A + bi * STAGE_B1;
        // B fragments [ks][4]: n16 x k16 tile per ks
        uint32_t bfr[4][4];
        #pragma unroll
        for (int ks = 0; ks < 4; ++ks) {
            int n = wn * 16 + (lane & 7) + (lane >> 4) * 8;
            int k = ks * 16 + ((lane >> 3) & 1) * 8;
            LDMX4(bfr[ks], sB + n * A_STRIDE + k * 2);
        }
        #pragma unroll
        for (int mt = 0; mt < 2; ++mt)
            #pragma unroll
            for (int nt = 0; nt < 2; ++nt)
                #pragma unroll
                for (int ks = 0; ks < 4; ++ks)
                    MMA16816(acc[bi][mt][nt], afr[mt][ks],
                             bfr[ks][nt * 2], bfr[ks][nt * 2 + 1]);
    }
}

// ---------------------------------------------------------------------------
// Fused conv (3 overlapping GEMMs), fp16 mma.sync, fp32 accum.
// Grid (16 f-tiles, 128 batches), 512 threads = 16 warps (4 m x 4 n),
// CTA tile 128 pos x 64 feat, warp tile 32x16; KC=64;
// 4-stage cp.async pipeline, one barrier per chunk; 3 compile-time phases.
// ---------------------------------------------------------------------------
__global__ __launch_bounds__(NTHR, 1)
void conv_tc(const float* __restrict__ b2, const float* __restrict__ b3,
             const float* __restrict__ b4, float* __restrict__ out)
{
    extern __shared__ char sm[];
    const uint32_t sb = smem_u32(sm);
    __shared__ float s_bias[3][64];

    const int tid  = threadIdx.x;
    const int lane = tid & 31;
    const int wid  = tid >> 5;
    const int wm   = wid & 3;        // 4 m-groups (32 pos each)
    const int wn   = wid >> 2;       // 4 n-groups (16 feats each)
    const int f0   = blockIdx.x * 64;
    const int b    = blockIdx.y;

    if (tid < 64) {
        s_bias[0][tid] = b2[f0 + tid];
        s_bias[1][tid] = b3[f0 + tid];
        s_bias[2][tid] = b4[f0 + tid];
    }

    const int    Ks[3]    = {K2, K3, K4};
    const size_t wbase[3] = {0, (size_t)NF * K2, (size_t)NF * (K2 + K3)};
    const size_t xbase    = (size_t)b * LSEQ * DIM;

    float acc[3][2][2][4];
    #pragma unroll
    for (int bi = 0; bi < 3; ++bi)
        #pragma unroll
        for (int mt = 0; mt < 2; ++mt)
            #pragma unroll
            for (int nt = 0; nt < 2; ++nt)
                #pragma unroll
                for (int q = 0; q < 4; ++q) acc[bi][mt][nt][q] = 0.f;

    auto issue_loads = [&](int st, int ch) {
        const int j0 = ch * KC;
        const uint32_t sst = sb + st * STAGE_SZ;
        // A: 128 rows x 8 x 16B = 1024 ops / 512 thr = 2
        #pragma unroll
        for (int p = 0; p < 2; ++p) {
            int idx = tid + p * NTHR;
            int row = idx >> 3, c = idx & 7;
            const __half* src = g_X + xbase + (size_t)row * DIM + j0 + c * 8;
            CP_ASYNC16(sst + row * A_STRIDE + c * 16, src);
        }
        // B per active branch: 64 rows x 8 = 512 ops / 512 thr = 1
        #pragma unroll
        for (int bi = 0; bi < 3; ++bi) {
            if (j0 >= Ks[bi]) continue;
            const uint32_t sB = sst + STAGE_A + bi * STAGE_B1;
            int row = tid >> 3, c = tid & 7;
            const __half* src = g_W + wbase[bi] + (size_t)(f0 + row) * Ks[bi] + j0 + c * 8;
            CP_ASYNC16(sB + row * A_STRIDE + c * 16, src);
        }
        CP_COMMIT();
    };

    auto step_pre = [&](int ch) {
        if (ch + 2 < NCHUNK) { issue_loads((ch + 2) % NSTAGE, ch + 2); CP_WAIT(2); }
        else if (ch + 1 < NCHUNK) { CP_WAIT(1); }
        else { CP_WAIT(0); }
        __syncthreads();
    };

    issue_loads(0, 0);
    issue_loads(1, 1);

    // Phase 1: branches {0,1,2}
    for (int ch = 0; ch < PH1; ++ch) {
        step_pre(ch);
        do_chunk<3>(sb + (ch % NSTAGE) * STAGE_SZ, lane, wm, wn, acc);
    }
    // Phase 2: branches {1,2}
    for (int ch = PH1; ch < PH2; ++ch) {
        step_pre(ch);
        do_chunk<2>(sb + (ch % NSTAGE) * STAGE_SZ, lane, wm, wn, acc);
    }
    // Phase 3: branch {2}
    for (int ch = PH2; ch < NCHUNK; ++ch) {
        step_pre(ch);
        do_chunk<1>(sb + (ch % NSTAGE) * STAGE_SZ, lane, wm, wn, acc);
    }

    // ---- epilogue: bias+relu+branch max -> smem [64f][132] -> coalesced out ----
    // sOut sits in stage 0 region; lagging warps only touch stage 3 (chunk 47).
    float* sOut = (float*)sm;
    #pragma unroll
    for (int mt = 0; mt < 2; ++mt)
        #pragma unroll
        for (int nt = 0; nt < 2; ++nt) {
            int mb = wm * 32 + mt * 16 + (lane >> 2);
            int n0 = wn * 16 + nt * 8 + (lane & 3) * 2;
            #pragma unroll
            for (int h = 0; h < 2; ++h) {
                int l = mb + h * 8;
                #pragma unroll
                for (int q = 0; q < 2; ++q) {
                    int fl = n0 + q;
                    float va = fmaxf(acc[0][mt][nt][h * 2 + q] + s_bias[0][fl], 0.f);
                    float vb = fmaxf(acc[1][mt][nt][h * 2 + q] + s_bias[1][fl], 0.f);
                    float vc = fmaxf(acc[2][mt][nt][h * 2 + q] + s_bias[2][fl], 0.f);
                    float v;
                    if (l < LOUT - 2)       v = fmaxf(fmaxf(va, vb), vc);
                    else if (l == LOUT - 2) v = fmaxf(va, vb);
                    else                    v = va;     // l >= 126 not stored
                    sOut[fl * 132 + l] = v;
                }
            }
        }
    __syncthreads();

    for (int idx = tid; idx < 64 * LOUT; idx += NTHR) {
        int f = idx / LOUT, l = idx % LOUT;
        out[((size_t)b * NF + f0 + f) * LOUT + l] = sOut[f * 132 + l];
    }
}

// ---------------------------------------------------------------------------
// L2-normalize over features: 3 coalesced passes
// ---------------------------------------------------------------------------
__global__ void norm_pass1(const float* __restrict__ out) {
    const int fg = blockIdx.x, b = blockIdx.y;
    const int l = threadIdx.x;
    float s = 0.f;
    if (l < LOUT) {
        const float* base = out + ((size_t)b * NF + fg * 128) * LOUT + l;
        for (int f = 0; f < 128; ++f) {
            float v = base[(size_t)f * LOUT];
            s += v * v;
        }
    }
    g_part[((size_t)b * 8 + fg) * 128 + l] = s;
}

__global__ void norm_pass2() {
    const int b = blockIdx.x, l = threadIdx.x;
    float s = 0.f;
    #pragma unroll
    for (int g = 0; g < 8; ++g) s += g_part[((size_t)b * 8 + g) * 128 + l];
    g_rn[b * 128 + l] = 1.f / fmaxf(sqrtf(s), 1e-12f);
}

__global__ void norm_pass3(float* __restrict__ out) {
    const int n = NB * NF * LOUT;
    for (int i = blockIdx.x * blockDim.x + threadIdx.x; i < n; i += gridDim.x * blockDim.x) {
        int l = i % LOUT;
        int b = i / (NF * LOUT);
        out[i] *= g_rn[b * 128 + l];
    }
}

// ---------------------------------------------------------------------------
// Sentence head
// ---------------------------------------------------------------------------
__global__ void sent_kernel(const float* __restrict__ S, const float* __restrict__ Wp,
                            const float* __restrict__ bp, float* __restrict__ out)
{
    const int b = blockIdx.x;
    __shared__ float xs[DIM];
    __shared__ float vals[NF];
    __shared__ float red[256];
    const int tid = threadIdx.x;
    const int warp = tid >> 5, lane = tid & 31;

    for (int i = tid; i < DIM; i += 256) xs[i] = S[(size_t)b * DIM + i];
    __syncthreads();

    for (int f = warp; f < NF; f += 8) {
        const float* w = Wp + (size_t)f * DIM;
        float acc = 0.f;
        #pragma unroll
        for (int d0 = 0; d0 < DIM; d0 += 128) {
            int d = d0 + lane * 4;
            float4 wv = *(const float4*)(w + d);
            acc += xs[d] * wv.x + xs[d + 1] * wv.y + xs[d + 2] * wv.z + xs[d + 3] * wv.w;
        }
        #pragma unroll
        for (int o = 16; o > 0; o >>= 1) acc += __shfl_down_sync(0xffffffffu, acc, o);
        if (lane == 0) vals[f] = acc + bp[f];
    }
    __syncthreads();

    float s = 0.f;
    for (int f = tid; f < NF; f += 256) s += vals[f] * vals[f];
    red[tid] = s;
    __syncthreads();
    for (int o = 128; o > 0; o >>= 1) {
        if (tid < o) red[tid] += red[tid + o];
        __syncthreads();
    }
    float n = fmaxf(sqrtf(red[0]), 1e-12f);

    for (int f = tid; f < NF; f += 256)
        out[(size_t)b * NF + f] = vals[f] / n;
}

// ---------------------------------------------------------------------------
// Launch (conv at index 3 = the ncu capture slot)
// ---------------------------------------------------------------------------
extern "C" void kernel_launch(void* const* d_in, const int* in_sizes, int n_in,
                              void* d_out, int out_size)
{
    const float* X  = (const float*)d_in[0];
    const float* S  = (const float*)d_in[1];
    const float* W2 = (const float*)d_in[2];
    const float* b2 = (const float*)d_in[3];
    const float* W3 = (const float*)d_in[4];
    const float* b3 = (const float*)d_in[5];
    const float* W4 = (const float*)d_in[6];
    const float* b4 = (const float*)d_in[7];
    const float* Wp = (const float*)d_in[8];
    const float* bp = (const float*)d_in[9];
    float* out = (float*)d_out;

    static int smem_set = 0;
    if (!smem_set) {
        cudaFuncSetAttribute(conv_tc, cudaFuncAttributeMaxDynamicSharedMemorySize, SMEM_DYN);
        smem_set = 1;
    }

    cvt_x_kernel<<<1024, 256>>>(X);                                      // 0
    cvt_w_kernel<<<1024, 256>>>(W2, W3, W4);                             // 1
    sent_kernel<<<NB, 256>>>(S, Wp, bp, out + (size_t)NB * NF * LOUT);   // 2
    conv_tc<<<dim3(16, NB), NTHR, SMEM_DYN>>>(b2, b3, b4, out);          // 3 <- ncu slot
    norm_pass1<<<dim3(8, NB), 128>>>(out);                               // 4
    norm_pass2<<<NB, 128>>>();                                           // 5
    norm_pass3<<<2048, 256>>>(out);                                      // 6
}

// round 9
// speedup vs baseline: 1.0840x; 1.0840x over previous
#include <cuda_runtime.h>
#include <cuda_fp16.h>
#include <math.h>
#include <stdint.h>

// ---------------------------------------------------------------------------
// Problem constants
// ---------------------------------------------------------------------------
#define NB    128
#define LSEQ  128
#define DIM   768
#define NF    1024
#define LOUT  126
#define NROWS (NB * LSEQ)

#define K2    1536
#define K3    2304
#define K4    3072
#define KTOT  3072
#define KC    64             // K per chunk (fp16 elems) -> 128B row
#define NCHUNK (KTOT / KC)   // 48
#define PH1   (K2 / KC)      // 24: chunks with 3 active branches
#define PH2   (K3 / KC)      // 36: chunks with 2 active branches

#define NTHR  256            // 8 warps: 4 m-groups x 2 n-groups
#define TFEAT 32             // CTA feature tile

// smem layout (bytes)
#define A_STRIDE  144                        // 64 fp16 (128B) + 16B pad
#define STAGE_A   (128 * A_STRIDE)           // 18432
#define STAGE_B1  (TFEAT * A_STRIDE)         // 4608
#define STAGE_SZ  (STAGE_A + 3 * STAGE_B1)   // 32256
#define NSTAGE    3
#define SMEM_DYN  (NSTAGE * STAGE_SZ)        // 96768 -> 2 CTAs/SM

// ---------------------------------------------------------------------------
// Scratch (device globals; no allocations allowed)
// ---------------------------------------------------------------------------
__device__ __half g_X[(NROWS + 8) * DIM];
#define WTOT (NF * (K2 + K3 + K4))
__device__ __half g_W[WTOT];
__device__ float g_part[NB * 8 * 128];
__device__ float g_rn[NB * 128];

// ---------------------------------------------------------------------------
// Baseline-PTX helpers (sm_80-class; compile under compute_103)
// ---------------------------------------------------------------------------
static __device__ __forceinline__ uint32_t smem_u32(const void* p) {
    uint32_t a;
    asm("{ .reg .u64 t; cvta.to.shared.u64 t, %1; cvt.u32.u64 %0, t; }"
        : "=r"(a) : "l"(p));
    return a;
}

#define CP_ASYNC16(dst, src) \
    asm volatile("cp.async.cg.shared.global [%0], [%1], 16;" \
                 :: "r"(dst), "l"(src) : "memory")
#define CP_COMMIT() asm volatile("cp.async.commit_group;" ::: "memory")
#define CP_WAIT(n)  asm volatile("cp.async.wait_group %0;" :: "n"(n) : "memory")

#define LDMX4(r, addr) \
    asm volatile("ldmatrix.sync.aligned.m8n8.x4.shared.b16 {%0,%1,%2,%3}, [%4];" \
                 : "=r"((r)[0]), "=r"((r)[1]), "=r"((r)[2]), "=r"((r)[3]) \
                 : "r"(addr))

#define MMA16816(d, a, b0v, b1v) \
    asm volatile("mma.sync.aligned.m16n8k16.row.col.f32.f16.f16.f32 " \
                 "{%0,%1,%2,%3},{%4,%5,%6,%7},{%8,%9},{%0,%1,%2,%3};" \
                 : "+f"((d)[0]), "+f"((d)[1]), "+f"((d)[2]), "+f"((d)[3]) \
                 : "r"((a)[0]), "r"((a)[1]), "r"((a)[2]), "r"((a)[3]), \
                   "r"(b0v), "r"(b1v))

// ---------------------------------------------------------------------------
// Prep: fp32 -> fp16
// ---------------------------------------------------------------------------
__global__ void cvt_x_kernel(const float* __restrict__ X) {
    const int n2 = (NROWS + 8) * DIM / 2;
    const int lim2 = NROWS * DIM / 2;
    __half2* dst = (__half2*)g_X;
    for (int i = blockIdx.x * blockDim.x + threadIdx.x; i < n2; i += gridDim.x * blockDim.x) {
        float2 v = (i < lim2) ? *(const float2*)(X + 2 * i) : make_float2(0.f, 0.f);
        dst[i] = __floats2half2_rn(v.x, v.y);
    }
}

__global__ void cvt_w_kernel(const float* __restrict__ W2, const float* __restrict__ W3,
                             const float* __restrict__ W4) {
    const int n2 = WTOT / 2;
    __half2* dst = (__half2*)g_W;
    for (int i = blockIdx.x * blockDim.x + threadIdx.x; i < n2; i += gridDim.x * blockDim.x) {
        int j = 2 * i;
        const float* src;
        if (j < NF * K2)             src = W2 + j;
        else if (j < NF * (K2 + K3)) src = W3 + (j - NF * K2);
        else                         src = W4 + (j - NF * (K2 + K3));
        float2 v = *(const float2*)src;
        dst[i] = __floats2half2_rn(v.x, v.y);
    }
}

// ---------------------------------------------------------------------------
// Per-chunk compute body. NBR = number of active branches (the LAST NBR of
// {K2,K3,K4}); fully compile-time. Warp tile 32 pos x 16 feat.
// ---------------------------------------------------------------------------
template<int NBR>
static __device__ __forceinline__ void do_chunk(
    uint32_t sA, int lane, int wm, int wn, float (&acc)[3][2][2][4])
{
    // A fragments [mt][ks][4]: 16x16 tiles
    uint32_t afr[2][4][4];
    #pragma unroll
    for (int mt = 0; mt < 2; ++mt)
        #pragma unroll
        for (int ks = 0; ks < 4; ++ks) {
            int m = wm * 32 + mt * 16 + (lane & 7) + ((lane >> 3) & 1) * 8;
            int k = ks * 16 + (lane >> 4) * 8;
            LDMX4(afr[mt][ks], sA + m * A_STRIDE + k * 2);
        }

    #pragma unroll
    for (int biR = 0; biR < NBR; ++biR) {
        const int bi = 3 - NBR + biR;
        const uint32_t sB = sA + STAGE_A + bi * STAGE_B1;
        // B fragments [ks][4]: n16 x k16 tile per ks
        uint32_t bfr[4][4];
        #pragma unroll
        for (int ks = 0; ks < 4; ++ks) {
            int n = wn * 16 + (lane & 7) + (lane >> 4) * 8;
            int k = ks * 16 + ((lane >> 3) & 1) * 8;
            LDMX4(bfr[ks], sB + n * A_STRIDE + k * 2);
        }
        #pragma unroll
        for (int mt = 0; mt < 2; ++mt)
            #pragma unroll
            for (int nt = 0; nt < 2; ++nt)
                #pragma unroll
                for (int ks = 0; ks < 4; ++ks)
                    MMA16816(acc[bi][mt][nt], afr[mt][ks],
                             bfr[ks][nt * 2], bfr[ks][nt * 2 + 1]);
    }
}

// ---------------------------------------------------------------------------
// Fused conv (3 overlapping GEMMs), fp16 mma.sync, fp32 accum.
// Grid (32 f-tiles, 128 batches), 256 threads = 8 warps (4 m x 2 n),
// CTA tile 128 pos x 32 feat, warp tile 32x16; KC=64;
// 3-stage cp.async (distance 1), one barrier per chunk; TWO CTAs PER SM so
// the per-CTA barriers interleave instead of phase-locking the whole SM.
// ---------------------------------------------------------------------------
__global__ __launch_bounds__(NTHR, 2)
void conv_tc(const float* __restrict__ b2, const float* __restrict__ b3,
             const float* __restrict__ b4, float* __restrict__ out)
{
    extern __shared__ char sm[];
    const uint32_t sb = smem_u32(sm);
    __shared__ float s_bias[3][TFEAT];

    const int tid  = threadIdx.x;
    const int lane = tid & 31;
    const int wid  = tid >> 5;
    const int wm   = wid & 3;        // 4 m-groups (32 pos each)
    const int wn   = wid >> 2;       // 2 n-groups (16 feats each)
    const int f0   = blockIdx.x * TFEAT;
    const int b    = blockIdx.y;

    if (tid < TFEAT) {
        s_bias[0][tid] = b2[f0 + tid];
        s_bias[1][tid] = b3[f0 + tid];
        s_bias[2][tid] = b4[f0 + tid];
    }

    const int    Ks[3]    = {K2, K3, K4};
    const size_t wbase[3] = {0, (size_t)NF * K2, (size_t)NF * (K2 + K3)};
    const size_t xbase    = (size_t)b * LSEQ * DIM;

    float acc[3][2][2][4];
    #pragma unroll
    for (int bi = 0; bi < 3; ++bi)
        #pragma unroll
        for (int mt = 0; mt < 2; ++mt)
            #pragma unroll
            for (int nt = 0; nt < 2; ++nt)
                #pragma unroll
                for (int q = 0; q < 4; ++q) acc[bi][mt][nt][q] = 0.f;

    auto issue_loads = [&](int st, int ch) {
        const int j0 = ch * KC;
        const uint32_t sst = sb + st * STAGE_SZ;
        // A: 128 rows x 8 x 16B = 1024 ops / 256 thr = 4
        #pragma unroll
        for (int p = 0; p < 4; ++p) {
            int idx = tid + p * NTHR;
            int row = idx >> 3, c = idx & 7;
            const __half* src = g_X + xbase + (size_t)row * DIM + j0 + c * 8;
            CP_ASYNC16(sst + row * A_STRIDE + c * 16, src);
        }
        // B per active branch: 32 rows x 8 = 256 ops / 256 thr = 1
        #pragma unroll
        for (int bi = 0; bi < 3; ++bi) {
            if (j0 >= Ks[bi]) continue;
            const uint32_t sB = sst + STAGE_A + bi * STAGE_B1;
            int row = tid >> 3, c = tid & 7;
            const __half* src = g_W + wbase[bi] + (size_t)(f0 + row) * Ks[bi] + j0 + c * 8;
            CP_ASYNC16(sB + row * A_STRIDE + c * 16, src);
        }
        CP_COMMIT();
    };

    // Distance-1 prefetch on a 3-stage ring: writer stage (ch+1)%3 never
    // collides with the current reader (ch)%3 nor a lagging reader (ch-1)%3,
    // so no trailing barrier is needed.
    auto step_pre = [&](int ch) {
        if (ch + 1 < NCHUNK) { issue_loads((ch + 1) % NSTAGE, ch + 1); CP_WAIT(1); }
        else { CP_WAIT(0); }
        __syncthreads();
    };

    issue_loads(0, 0);

    // Phase 1: branches {0,1,2}
    for (int ch = 0; ch < PH1; ++ch) {
        step_pre(ch);
        do_chunk<3>(sb + (ch % NSTAGE) * STAGE_SZ, lane, wm, wn, acc);
    }
    // Phase 2: branches {1,2}
    for (int ch = PH1; ch < PH2; ++ch) {
        step_pre(ch);
        do_chunk<2>(sb + (ch % NSTAGE) * STAGE_SZ, lane, wm, wn, acc);
    }
    // Phase 3: branch {2}
    for (int ch = PH2; ch < NCHUNK; ++ch) {
        step_pre(ch);
        do_chunk<1>(sb + (ch % NSTAGE) * STAGE_SZ, lane, wm, wn, acc);
    }

    // ---- epilogue: bias+relu+branch max -> smem [32f][132] -> coalesced out ----
    // sOut occupies [0, 16896) inside stage 0; the last chunk (47) reads stage
    // 47%3=2 -> no overlap with laggards.
    float* sOut = (float*)sm;
    #pragma unroll
    for (int mt = 0; mt < 2; ++mt)
        #pragma unroll
        for (int nt = 0; nt < 2; ++nt) {
            int mb = wm * 32 + mt * 16 + (lane >> 2);
            int n0 = wn * 16 + nt * 8 + (lane & 3) * 2;
            #pragma unroll
            for (int h = 0; h < 2; ++h) {
                int l = mb + h * 8;
                #pragma unroll
                for (int q = 0; q < 2; ++q) {
                    int fl = n0 + q;
                    float va = fmaxf(acc[0][mt][nt][h * 2 + q] + s_bias[0][fl], 0.f);
                    float vb = fmaxf(acc[1][mt][nt][h * 2 + q] + s_bias[1][fl], 0.f);
                    float vc = fmaxf(acc[2][mt][nt][h * 2 + q] + s_bias[2][fl], 0.f);
                    float v;
                    if (l < LOUT - 2)       v = fmaxf(fmaxf(va, vb), vc);
                    else if (l == LOUT - 2) v = fmaxf(va, vb);
                    else                    v = va;     // l >= 126 not stored
                    sOut[fl * 132 + l] = v;
                }
            }
        }
    __syncthreads();

    for (int idx = tid; idx < TFEAT * LOUT; idx += NTHR) {
        int f = idx / LOUT, l = idx % LOUT;
        out[((size_t)b * NF + f0 + f) * LOUT + l] = sOut[f * 132 + l];
    }
}

// ---------------------------------------------------------------------------
// L2-normalize over features: 3 coalesced passes
// ---------------------------------------------------------------------------
__global__ void norm_pass1(const float* __restrict__ out) {
    const int fg = blockIdx.x, b = blockIdx.y;
    const int l = threadIdx.x;
    float s = 0.f;
    if (l < LOUT) {
        const float* base = out + ((size_t)b * NF + fg * 128) * LOUT + l;
        for (int f = 0; f < 128; ++f) {
            float v = base[(size_t)f * LOUT];
            s += v * v;
        }
    }
    g_part[((size_t)b * 8 + fg) * 128 + l] = s;
}

__global__ void norm_pass2() {
    const int b = blockIdx.x, l = threadIdx.x;
    float s = 0.f;
    #pragma unroll
    for (int g = 0; g < 8; ++g) s += g_part[((size_t)b * 8 + g) * 128 + l];
    g_rn[b * 128 + l] = 1.f / fmaxf(sqrtf(s), 1e-12f);
}

__global__ void norm_pass3(float* __restrict__ out) {
    const int n = NB * NF * LOUT;
    for (int i = blockIdx.x * blockDim.x + threadIdx.x; i < n; i += gridDim.x * blockDim.x) {
        int l = i % LOUT;
        int b = i / (NF * LOUT);
        out[i] *= g_rn[b * 128 + l];
    }
}

// ---------------------------------------------------------------------------
// Sentence head
// ---------------------------------------------------------------------------
__global__ void sent_kernel(const float* __restrict__ S, const float* __restrict__ Wp,
                            const float* __restrict__ bp, float* __restrict__ out)
{
    const int b = blockIdx.x;
    __shared__ float xs[DIM];
    __shared__ float vals[NF];
    __shared__ float red[256];
    const int tid = threadIdx.x;
    const int warp = tid >> 5, lane = tid & 31;

    for (int i = tid; i < DIM; i += 256) xs[i] = S[(size_t)b * DIM + i];
    __syncthreads();

    for (int f = warp; f < NF; f += 8) {
        const float* w = Wp + (size_t)f * DIM;
        float acc = 0.f;
        #pragma unroll
        for (int d0 = 0; d0 < DIM; d0 += 128) {
            int d = d0 + lane * 4;
            float4 wv = *(const float4*)(w + d);
            acc += xs[d] * wv.x + xs[d + 1] * wv.y + xs[d + 2] * wv.z + xs[d + 3] * wv.w;
        }
        #pragma unroll
        for (int o = 16; o > 0; o >>= 1) acc += __shfl_down_sync(0xffffffffu, acc, o);
        if (lane == 0) vals[f] = acc + bp[f];
    }
    __syncthreads();

    float s = 0.f;
    for (int f = tid; f < NF; f += 256) s += vals[f] * vals[f];
    red[tid] = s;
    __syncthreads();
    for (int o = 128; o > 0; o >>= 1) {
        if (tid < o) red[tid] += red[tid + o];
        __syncthreads();
    }
    float n = fmaxf(sqrtf(red[0]), 1e-12f);

    for (int f = tid; f < NF; f += 256)
        out[(size_t)b * NF + f] = vals[f] / n;
}

// ---------------------------------------------------------------------------
// Launch (conv at index 3 = the ncu capture slot)
// ---------------------------------------------------------------------------
extern "C" void kernel_launch(void* const* d_in, const int* in_sizes, int n_in,
                              void* d_out, int out_size)
{
    const float* X  = (const float*)d_in[0];
    const float* S  = (const float*)d_in[1];
    const float* W2 = (const float*)d_in[2];
    const float* b2 = (const float*)d_in[3];
    const float* W3 = (const float*)d_in[4];
    const float* b3 = (const float*)d_in[5];
    const float* W4 = (const float*)d_in[6];
    const float* b4 = (const float*)d_in[7];
    const float* Wp = (const float*)d_in[8];
    const float* bp = (const float*)d_in[9];
    float* out = (float*)d_out;

    static int smem_set = 0;
    if (!smem_set) {
        cudaFuncSetAttribute(conv_tc, cudaFuncAttributeMaxDynamicSharedMemorySize, SMEM_DYN);
        smem_set = 1;
    }

    cvt_x_kernel<<<1024, 256>>>(X);                                      // 0
    cvt_w_kernel<<<1024, 256>>>(W2, W3, W4);                             // 1
    sent_kernel<<<NB, 256>>>(S, Wp, bp, out + (size_t)NB * NF * LOUT);   // 2
    conv_tc<<<dim3(32, NB), NTHR, SMEM_DYN>>>(b2, b3, b4, out);          // 3 <- ncu slot
    norm_pass1<<<dim3(8, NB), 128>>>(out);                               // 4
    norm_pass2<<<NB, 128>>>();                                           // 5
    norm_pass3<<<2048, 256>>>(out);                                      // 6
}